// round 3
// baseline (speedup 1.0000x reference)
#include <cuda_runtime.h>
#include <cuda_bf16.h>
#include <cstdint>

// scratch for the 4-channel logits (pre-scaled by log2(e)) on the 14^3 grid
__device__ float g_z[4 * 14 * 14 * 14];

#define LOG2E 1.4426950408889634f

// ---------------------------------------------------------------------------
// Kernel 1: 1x1x1 conv on the small grid, output pre-multiplied by log2(e) so
// the big kernel can use raw exp2 (single MUFU.EX2 per element).
// ---------------------------------------------------------------------------
__global__ void conv_small_kernel(const float* __restrict__ x,
                                  const float* __restrict__ W,
                                  const float* __restrict__ b) {
    int idx = blockIdx.x * blockDim.x + threadIdx.x;
    if (idx >= 4 * 2744) return;
    int o = idx / 2744;
    int v = idx - o * 2744;
    float acc = b[o];
    const float* wrow = W + o * 32;
#pragma unroll
    for (int c = 0; c < 32; c++) {
        acc = fmaf(wrow[c], x[c * 2744 + v], acc);
    }
    g_z[idx] = acc * LOG2E;
}

// ---------------------------------------------------------------------------
// Kernel 2: block (56, 8) handles one d and 8 consecutive h rows.
//  Phase A: per-row bilinear (d,h) lerp of the 14-wide 4-channel line into
//           smem; per-w interpolation table (iw0, ww).
//  Phase B: each thread computes 4 consecutive w voxels (lerp in log2 domain,
//           softmax via exp2 + rcp.approx) and writes results to a smem slab
//           sdata[c][row][w] with STS.128.
//  Phase C: one thread issues 4 x cp.async.bulk (1D shared->global, 7168B per
//           channel plane) on the TMA pipe -- replaces 3584 STG.128 per block.
// ---------------------------------------------------------------------------
__global__ __launch_bounds__(448) void upsample_softmax_kernel(float* __restrict__ out) {
    __shared__ __align__(16) float sdata[4][8][224];  // 28672 B
    __shared__ float4 gs[8][14];                       // per-row lerped lines
    __shared__ float  sww[224];
    __shared__ int    siw[224];

    const int tx = threadIdx.x;          // 0..55
    const int ty = threadIdx.y;          // 0..7
    const int d  = blockIdx.y;
    const int h  = blockIdx.x * 8 + ty;
    const float scale = 13.0f / 223.0f;  // align_corners=True

    // ---- Phase A: fill gs and the per-w table ----
    {
        float pd = (float)d * scale;
        int id0 = (int)pd; if (id0 > 12) id0 = 12;
        float wd = pd - (float)id0;
        float ph = (float)h * scale;
        int ih0 = (int)ph; if (ih0 > 12) ih0 = 12;
        float wh = ph - (float)ih0;

        int iw = tx >> 2, c = tx & 3;
        const float* zb = g_z + c * 2744;
        int base = (id0 * 14 + ih0) * 14 + iw;
        float z00 = zb[base];
        float z01 = zb[base + 14];
        float z10 = zb[base + 196];
        float z11 = zb[base + 210];
        float a0 = fmaf(wh, z01 - z00, z00);
        float a1 = fmaf(wh, z11 - z10, z10);
        ((float*)gs[ty])[tx] = fmaf(wd, a1 - a0, a0);
    }
    {
        int lin = ty * 56 + tx;
        if (lin < 224) {
            float pw = (float)lin * scale;
            int iw0 = (int)pw; if (iw0 > 12) iw0 = 12;
            siw[lin] = iw0;
            sww[lin] = pw - (float)iw0;
        }
    }
    __syncthreads();

    // ---- Phase B: compute 4 voxels, stage into smem slab ----
    const int w0 = tx * 4;
    float r0[4], r1[4], r2[4], r3[4];

#pragma unroll
    for (int k = 0; k < 4; k++) {
        int w = w0 + k;
        int iw = siw[w];
        float ww = sww[w];
        float4 A = gs[ty][iw];
        float4 B = gs[ty][iw + 1];
        float z0 = fmaf(ww, B.x - A.x, A.x);
        float z1 = fmaf(ww, B.y - A.y, A.y);
        float z2 = fmaf(ww, B.z - A.z, A.z);
        float z3 = fmaf(ww, B.w - A.w, A.w);
        float e0 = exp2f(z0);
        float e1 = exp2f(z1);
        float e2 = exp2f(z2);
        float e3 = exp2f(z3);
        float s = (e0 + e1) + (e2 + e3);
        float rr;
        asm("rcp.approx.f32 %0, %1;" : "=f"(rr) : "f"(s));
        r0[k] = e0 * rr;
        r1[k] = e1 * rr;
        r2[k] = e2 * rr;
        r3[k] = e3 * rr;
    }

    *(float4*)&sdata[0][ty][w0] = make_float4(r0[0], r0[1], r0[2], r0[3]);
    *(float4*)&sdata[1][ty][w0] = make_float4(r1[0], r1[1], r1[2], r1[3]);
    *(float4*)&sdata[2][ty][w0] = make_float4(r2[0], r2[1], r2[2], r2[3]);
    *(float4*)&sdata[3][ty][w0] = make_float4(r3[0], r3[1], r3[2], r3[3]);

    __syncthreads();

    // ---- Phase C: bulk async store, one 7168B copy per channel plane ----
    if (tx == 0 && ty == 0) {
        asm volatile("fence.proxy.async.shared::cta;" ::: "memory");

        const long long PLANE = 224LL * 224 * 224;
        const int h0 = blockIdx.x * 8;
        float* gbase = out + ((long long)d * 224 + h0) * 224;

        uint32_t saddr;
        asm("{ .reg .u64 t; cvta.to.shared.u64 t, %1; cvt.u32.u64 %0, t; }"
            : "=r"(saddr) : "l"((void*)&sdata[0][0][0]));

        const int CH_BYTES = 8 * 224 * 4;  // 7168
#pragma unroll
        for (int c = 0; c < 4; c++) {
            float* gptr = gbase + c * PLANE;
            asm volatile(
                "cp.async.bulk.global.shared::cta.bulk_group [%0], [%1], %2;"
                :: "l"(gptr), "r"(saddr + c * CH_BYTES), "n"(CH_BYTES)
                : "memory");
        }
        asm volatile("cp.async.bulk.commit_group;" ::: "memory");
        asm volatile("cp.async.bulk.wait_group 0;" ::: "memory");
    }
}

extern "C" void kernel_launch(void* const* d_in, const int* in_sizes, int n_in,
                              void* d_out, int out_size) {
    const float* x = (const float*)d_in[0];  // [1,32,14,14,14]
    const float* W = (const float*)d_in[1];  // [4,32]
    const float* b = (const float*)d_in[2];  // [4]
    float* out = (float*)d_out;              // [1,4,224,224,224]

    conv_small_kernel<<<(4 * 2744 + 255) / 256, 256>>>(x, W, b);

    dim3 block(56, 8);
    dim3 grid(28, 224);  // (h-group of 8, d)
    upsample_softmax_kernel<<<grid, block>>>(out);
}

// round 4
// speedup vs baseline: 1.0846x; 1.0846x over previous
#include <cuda_runtime.h>
#include <cuda_bf16.h>
#include <cstdint>

// scratch for the 4-channel logits (pre-scaled by log2(e)) on the 14^3 grid
__device__ float g_z[4 * 14 * 14 * 14];

#define LOG2E 1.4426950408889634f

// ---------------------------------------------------------------------------
// Kernel 1: 1x1x1 conv on the small grid, pre-multiplied by log2(e) so the
// big kernel uses raw MUFU.EX2.
// ---------------------------------------------------------------------------
__global__ void conv_small_kernel(const float* __restrict__ x,
                                  const float* __restrict__ W,
                                  const float* __restrict__ b) {
    int idx = blockIdx.x * blockDim.x + threadIdx.x;
    if (idx >= 4 * 2744) return;
    int o = idx / 2744;
    int v = idx - o * 2744;
    float acc = b[o];
    const float* wrow = W + o * 32;
#pragma unroll
    for (int c = 0; c < 32; c++) {
        acc = fmaf(wrow[c], x[c * 2744 + v], acc);
    }
    g_z[idx] = acc * LOG2E;
}

// ---------------------------------------------------------------------------
// Kernel 2: block (56, 8) = one d, 8 consecutive h rows. Fill: bilinear-lerp
// each row's 14-wide 4-channel line into smem (padded with a dup entry).
// Main: each thread handles 4 consecutive w. The 4 voxels cross at most one
// knot, so load G0,G1,G2 ONCE and evaluate the continuous piecewise-linear
// form  z = G0 + u*(G1-G0) + v*(G2-G1),  u=min(t,1), v=max(t-1,0).
// Zero shared-memory traffic inside the k-loop; softmax = 4x EX2 + RCP;
// 4x STG.128 per thread.
// ---------------------------------------------------------------------------
__global__ __launch_bounds__(448) void upsample_softmax_kernel(float* __restrict__ out) {
    __shared__ __align__(16) float4 gs[8][16];   // 15 used (14 + dup), pad to 16

    const int tx = threadIdx.x;          // 0..55
    const int ty = threadIdx.y;          // 0..7
    const int d  = blockIdx.y;
    const int h  = blockIdx.x * 8 + ty;
    const float scale = 13.0f / 223.0f;  // align_corners=True

    // ---- fill: this row's 56 floats (14 iw x 4 ch) + dup of iw=13 at 14 ----
    {
        float pd = (float)d * scale;
        int id0 = (int)pd; if (id0 > 12) id0 = 12;
        float wd = pd - (float)id0;
        float ph = (float)h * scale;
        int ih0 = (int)ph; if (ih0 > 12) ih0 = 12;
        float wh = ph - (float)ih0;

        int iw = tx >> 2, c = tx & 3;
        const float* zb = g_z + c * 2744;
        int base = (id0 * 14 + ih0) * 14 + iw;
        float z00 = zb[base];
        float z01 = zb[base + 14];
        float z10 = zb[base + 196];
        float z11 = zb[base + 210];
        float a0 = fmaf(wh, z01 - z00, z00);
        float a1 = fmaf(wh, z11 - z10, z10);
        float v  = fmaf(wd, a1 - a0, a0);
        ((float*)&gs[ty][iw])[c] = v;
        if (iw == 13) ((float*)&gs[ty][14])[c] = v;   // safe dup, never used
    }
    __syncthreads();

    // ---- per-thread: 4 consecutive w, all operands in registers ----
    const int w0 = tx * 4;
    float pw0 = (float)w0 * scale;
    int iw0 = (int)pw0; if (iw0 > 12) iw0 = 12;
    float t0 = pw0 - (float)iw0;

    float4 G0 = gs[ty][iw0];
    float4 G1 = gs[ty][iw0 + 1];
    float4 G2 = gs[ty][iw0 + 2];
    float4 D10 = make_float4(G1.x - G0.x, G1.y - G0.y, G1.z - G0.z, G1.w - G0.w);
    float4 D21 = make_float4(G2.x - G1.x, G2.y - G1.y, G2.z - G1.z, G2.w - G1.w);

    float r0[4], r1[4], r2[4], r3[4];

#pragma unroll
    for (int k = 0; k < 4; k++) {
        float t = t0 + (float)k * scale;       // k*scale folds to a constant
        float u = fminf(t, 1.0f);
        float v = fmaxf(t - 1.0f, 0.0f);
        float z0 = fmaf(v, D21.x, fmaf(u, D10.x, G0.x));
        float z1 = fmaf(v, D21.y, fmaf(u, D10.y, G0.y));
        float z2 = fmaf(v, D21.z, fmaf(u, D10.z, G0.z));
        float z3 = fmaf(v, D21.w, fmaf(u, D10.w, G0.w));
        float e0 = exp2f(z0);
        float e1 = exp2f(z1);
        float e2 = exp2f(z2);
        float e3 = exp2f(z3);
        float s = (e0 + e1) + (e2 + e3);
        float rr;
        asm("rcp.approx.f32 %0, %1;" : "=f"(rr) : "f"(s));
        r0[k] = e0 * rr;
        r1[k] = e1 * rr;
        r2[k] = e2 * rr;
        r3[k] = e3 * rr;
    }

    const int PLANE4 = (224 * 224 * 224) >> 2;
    int idx4 = (((d * 224 + h) * 224 + w0) >> 2);
    float4* o4 = (float4*)out;
    o4[idx4]              = make_float4(r0[0], r0[1], r0[2], r0[3]);
    o4[idx4 + PLANE4]     = make_float4(r1[0], r1[1], r1[2], r1[3]);
    o4[idx4 + 2 * PLANE4] = make_float4(r2[0], r2[1], r2[2], r2[3]);
    o4[idx4 + 3 * PLANE4] = make_float4(r3[0], r3[1], r3[2], r3[3]);
}

extern "C" void kernel_launch(void* const* d_in, const int* in_sizes, int n_in,
                              void* d_out, int out_size) {
    const float* x = (const float*)d_in[0];  // [1,32,14,14,14]
    const float* W = (const float*)d_in[1];  // [4,32]
    const float* b = (const float*)d_in[2];  // [4]
    float* out = (float*)d_out;              // [1,4,224,224,224]

    conv_small_kernel<<<(4 * 2744 + 255) / 256, 256>>>(x, W, b);

    dim3 block(56, 8);
    dim3 grid(28, 224);  // (h-group of 8, d)
    upsample_softmax_kernel<<<grid, block>>>(out);
}